// round 14
// baseline (speedup 1.0000x reference)
#include <cuda_runtime.h>
#include <cuda_bf16.h>
#include <math.h>
#include <stdint.h>

// ---------------------------------------------------------------------------
// SingleStreamBlock — tf32 mma.sync + cp.async, BK=32 (halved per-iter
// overhead), weights pre-rounded, activations rounded at source.
// Shapes: B=1, L=2048, D=3072, H=24, Dh=128, QKV=9216, CAT=15360
// ---------------------------------------------------------------------------

#define L_   2048
#define D_   3072
#define H_   24
#define DH_  128
#define QKV_ 9216
#define W1N_ 21504      // QKV + 4*D
#define CAT_ 15360      // D + 4*D
#define EPS_ 1e-6f

// Scratch (device globals: allocation-free)
__device__ float g_sv[D_];
__device__ float g_m[3 * D_];
__device__ float g_xmod[(size_t)L_ * D_];
__device__ float g_h[(size_t)L_ * QKV_];        // compact qkv
__device__ float g_S[(size_t)H_ * L_ * L_];
__device__ float g_cat[(size_t)L_ * CAT_];      // [attn | gelu(mlp)]
__device__ float g_w1r[(size_t)D_ * W1N_];      // tf32-rounded w1
__device__ float g_w2r[(size_t)CAT_ * D_];      // tf32-rounded w2

__device__ __forceinline__ uint32_t f2tf32(float x) {
    uint32_t r;
    asm("cvt.rna.tf32.f32 %0, %1;" : "=r"(r) : "f"(x));
    return r;
}
__device__ __forceinline__ float rnaf(float x) {
    return __uint_as_float(f2tf32(x));
}

// ---------------------------------------------------------------------------
// weight pre-round
// ---------------------------------------------------------------------------
__global__ void wround(const float4* __restrict__ w, float4* __restrict__ o, int n4) {
    int i = blockIdx.x * blockDim.x + threadIdx.x;
    int stride = gridDim.x * blockDim.x;
    for (; i < n4; i += stride) {
        float4 v = w[i];
        o[i] = make_float4(rnaf(v.x), rnaf(v.y), rnaf(v.z), rnaf(v.w));
    }
}

// ---------------------------------------------------------------------------
// small elementwise / reduction kernels
// ---------------------------------------------------------------------------
__global__ void silu_init(const float* __restrict__ v, const float* __restrict__ b,
                          float* __restrict__ sv, float* __restrict__ m) {
    int i = blockIdx.x * blockDim.x + threadIdx.x;
    if (i < D_) {
        float x = v[i];
        sv[i] = x / (1.0f + expf(-x));
    }
    if (i < 3 * D_) m[i] = b[i];
}

// partial dot over i-chunk of 192, atomicAdd into m. grid (72, 16), 128 thr
__global__ void mod_gemv(const float* __restrict__ sv, const float* __restrict__ w,
                         float* __restrict__ m) {
    __shared__ float s[192];
    int i0 = blockIdx.y * 192;
    for (int i = threadIdx.x; i < 192; i += 128) s[i] = sv[i0 + i];
    __syncthreads();
    int j = blockIdx.x * 128 + threadIdx.x;
    float acc = 0.f;
#pragma unroll 8
    for (int i = 0; i < 192; i++) acc += s[i] * w[(size_t)(i0 + i) * (3 * D_) + j];
    atomicAdd(&m[j], acc);
}

__global__ void ln_mod(const float* __restrict__ x, const float* __restrict__ m,
                       float* __restrict__ xmod) {
    __shared__ float r1[8], r2[8], bc[2];
    int row = blockIdx.x, t = threadIdx.x;
    const float* xr = x + (size_t)row * D_;
    float sum = 0.f, ss = 0.f;
    for (int i = t; i < D_; i += 256) {
        float v = xr[i];
        sum += v; ss += v * v;
    }
#pragma unroll
    for (int o = 16; o > 0; o >>= 1) {
        sum += __shfl_xor_sync(0xffffffffu, sum, o);
        ss  += __shfl_xor_sync(0xffffffffu, ss,  o);
    }
    if ((t & 31) == 0) { r1[t >> 5] = sum; r2[t >> 5] = ss; }
    __syncthreads();
    if (t == 0) {
        float a = 0.f, b = 0.f;
        for (int w = 0; w < 8; w++) { a += r1[w]; b += r2[w]; }
        bc[0] = a; bc[1] = b;
    }
    __syncthreads();
    float mu  = bc[0] * (1.0f / D_);
    float var = bc[1] * (1.0f / D_) - mu * mu;
    float inv = rsqrtf(var + EPS_);
    const float* shift = m;
    const float* scale = m + D_;
    float* orow = xmod + (size_t)row * D_;
    for (int i = t; i < D_; i += 256) {
        float v = (xr[i] - mu) * inv;
        orow[i] = rnaf((1.0f + scale[i]) * v + shift[i]);
    }
}

// RMSNorm + RoPE for q,k in compact h [L][QKV_]; tf32-rounded
__global__ void rmsrope(float* __restrict__ h, const float* __restrict__ pe,
                        const float* __restrict__ qs, const float* __restrict__ ks) {
    __shared__ float red[2];
    int l = blockIdx.x, hh = blockIdx.y, t = threadIdx.x;
    float* base = h + (size_t)l * QKV_ + hh * DH_;
    const float* p = pe + (size_t)l * 256 + t * 4;
    for (int s = 0; s < 2; s++) {
        float* ptr = base + s * D_;
        const float* g = s ? ks : qs;
        float a = ptr[2 * t], b = ptr[2 * t + 1];
        float sq = a * a + b * b;
#pragma unroll
        for (int o = 16; o > 0; o >>= 1) sq += __shfl_xor_sync(0xffffffffu, sq, o);
        if ((t & 31) == 0) red[t >> 5] = sq;
        __syncthreads();
        float tot = red[0] + red[1];
        float r = rsqrtf(tot * (1.0f / DH_) + EPS_);
        float na = a * r * g[2 * t];
        float nb = b * r * g[2 * t + 1];
        ptr[2 * t]     = rnaf(p[0] * na + p[1] * nb);
        ptr[2 * t + 1] = rnaf(p[2] * na + p[3] * nb);
        __syncthreads();
    }
}

__global__ void softmax2048(float* __restrict__ S) {
    __shared__ float r[8], bc;
    int t = threadIdx.x;
    float* row = S + (size_t)blockIdx.x * L_;
    float v[8];
    float mx = -1e30f;
#pragma unroll
    for (int i = 0; i < 8; i++) { v[i] = row[t + i * 256]; mx = fmaxf(mx, v[i]); }
#pragma unroll
    for (int o = 16; o > 0; o >>= 1) mx = fmaxf(mx, __shfl_xor_sync(0xffffffffu, mx, o));
    if ((t & 31) == 0) r[t >> 5] = mx;
    __syncthreads();
    if (t == 0) {
        float m2 = r[0];
        for (int w = 1; w < 8; w++) m2 = fmaxf(m2, r[w]);
        bc = m2;
    }
    __syncthreads();
    mx = bc;
    float sum = 0.f;
#pragma unroll
    for (int i = 0; i < 8; i++) { v[i] = expf(v[i] - mx); sum += v[i]; }
#pragma unroll
    for (int o = 16; o > 0; o >>= 1) sum += __shfl_xor_sync(0xffffffffu, sum, o);
    if ((t & 31) == 0) r[t >> 5] = sum;
    __syncthreads();
    if (t == 0) {
        float s2 = 0.f;
        for (int w = 0; w < 8; w++) s2 += r[w];
        bc = s2;
    }
    __syncthreads();
    float inv = 1.0f / bc;
#pragma unroll
    for (int i = 0; i < 8; i++) row[t + i * 256] = rnaf(v[i] * inv);
}

__device__ __forceinline__ float gelu_tanh(float x) {
    float x3 = x * x * x;
    return 0.5f * x * (1.0f + tanhf(0.7978845608028654f * (x + 0.044715f * x3)));
}

// ---------------------------------------------------------------------------
// tf32 mma.sync GEMM: cp.async 4-stage, BK=32, BM=BN=128. 256 thr = 8 warps
// (2m x 4n), warp tile 64x32. 1 CTA/SM (smem-bound), regs unclamped.
// A smem [m][k] stride 36 words (ldmatrix, conflict-free: 8-row starts 4r%32).
// B NT [n][k] stride 36 (ldmatrix). B NN [k][n] stride 136 (scalar LDS).
// EPI 1:*alpha | 2: rna (PV->cat) | 3: xres+gate*(acc+bias) | 4: h|gelu->cat
// ---------------------------------------------------------------------------
#define CPA16(dst, src) \
    asm volatile("cp.async.cg.shared.global [%0], [%1], 16;" :: "r"(dst), "l"(src))
#define CP_COMMIT() asm volatile("cp.async.commit_group;" ::: "memory")
#define CP_WAIT2()  asm volatile("cp.async.wait_group 2;" ::: "memory")

__device__ __forceinline__ void mma_tf32(float c[4], const uint32_t a[4],
                                         const uint32_t b[2]) {
    asm volatile(
        "mma.sync.aligned.m16n8k8.row.col.f32.tf32.tf32.f32 "
        "{%0,%1,%2,%3}, {%4,%5,%6,%7}, {%8,%9}, {%0,%1,%2,%3};"
        : "+f"(c[0]), "+f"(c[1]), "+f"(c[2]), "+f"(c[3])
        : "r"(a[0]), "r"(a[1]), "r"(a[2]), "r"(a[3]), "r"(b[0]), "r"(b[1]));
}
__device__ __forceinline__ void ldsm4(uint32_t* r, uint32_t addr) {
    asm volatile("ldmatrix.sync.aligned.m8n8.x4.shared.b16 {%0,%1,%2,%3}, [%4];"
                 : "=r"(r[0]), "=r"(r[1]), "=r"(r[2]), "=r"(r[3]) : "r"(addr));
}

template <int EPI, bool NT>
__global__ __launch_bounds__(256) void gemm_cp(
    const float* __restrict__ A, const float* __restrict__ B, float* __restrict__ C,
    float* __restrict__ C2,
    int K, int lda, int ldb, int ldc,
    long long sA, long long sB, long long sC, float alpha,
    const float* __restrict__ bias, const float* __restrict__ xres,
    const float* __restrict__ gate)
{
    constexpr int BK = 32;
    constexpr int AW = 128 * 36;                        // A stage words
    constexpr int BW = NT ? 128 * 36 : BK * 136;        // B stage words
    constexpr int STGW = AW + BW;
    constexpr int NJ = 4;
    extern __shared__ float sm[];

    A += (long long)blockIdx.z * sA;
    B += (long long)blockIdx.z * sB;
    C += (long long)blockIdx.z * sC;
    const int m0 = blockIdx.x * 128, n0 = blockIdx.y * 128;
    const int tid = threadIdx.x;
    const int warp = tid >> 5, lane = tid & 31;
    const int wm = (warp & 1) * 64;
    const int wn = (warp >> 1) * 32;
    const int g = lane >> 2, q = lane & 3;

    const uint32_t sbase = (uint32_t)__cvta_generic_to_shared(sm);

    // ldmatrix byte offsets at ksp=0 (add ksp*32 bytes at use)
    int aoff[4];
#pragma unroll
    for (int mi = 0; mi < 4; mi++)
        aoff[mi] = ((wm + mi * 16 + ((lane >> 3) & 1) * 8 + (lane & 7)) * 36
                    + ((lane >> 4) & 1) * 4) * 4;
    int boff[2];
    if (NT) {
#pragma unroll
        for (int njp = 0; njp < 2; njp++)
            boff[njp] = AW * 4 +
                ((wn + njp * 16 + ((lane >> 4) & 1) * 8 + (lane & 7)) * 36
                 + ((lane >> 3) & 1) * 4) * 4;
    }

    float acc[4][NJ][4];
#pragma unroll
    for (int mi = 0; mi < 4; mi++)
#pragma unroll
        for (int nj = 0; nj < NJ; nj++)
#pragma unroll
            for (int e = 0; e < 4; e++) acc[mi][nj][e] = 0.f;

    const int nk = K >> 5;

    auto issue = [&](int kt, int s) {
        const uint32_t as = sbase + (uint32_t)(s * STGW * 4);
        const uint32_t bs = as + AW * 4;
        const int k0 = kt << 5;
        // A: 128 rows x 32 k = 1024 chunks (4/thread)
#pragma unroll
        for (int i = 0; i < 4; i++) {
            int ch = tid + 256 * i;
            int r = ch >> 3, c = ch & 7;
            CPA16(as + (uint32_t)(r * 144 + c * 16),
                  A + (size_t)(m0 + r) * lda + k0 + c * 4);
        }
        if (NT) {   // B: 128 rows x 32 k
#pragma unroll
            for (int i = 0; i < 4; i++) {
                int ch = tid + 256 * i;
                int r = ch >> 3, c = ch & 7;
                CPA16(bs + (uint32_t)(r * 144 + c * 16),
                      B + (size_t)(n0 + r) * ldb + k0 + c * 4);
            }
        } else {    // B: 32 k x 128 cols
#pragma unroll
            for (int i = 0; i < 4; i++) {
                int ch = tid + 256 * i;
                int r = ch >> 5, c = ch & 31;
                CPA16(bs + (uint32_t)(r * 544 + c * 16),
                      B + (size_t)(k0 + r) * ldb + n0 + c * 4);
            }
        }
    };

    for (int s = 0; s < 3; s++) {
        if (s < nk) issue(s, s);
        CP_COMMIT();
    }

    for (int it = 0; it < nk; it++) {
        CP_WAIT2();
        __syncthreads();
        if (it + 3 < nk) issue(it + 3, (it + 3) & 3);
        CP_COMMIT();

        const uint32_t stg_u = sbase + (uint32_t)((it & 3) * STGW * 4);
        const float* bs = sm + (size_t)(it & 3) * STGW + AW;
#pragma unroll
        for (int ksp = 0; ksp < 4; ksp++) {
            const int kq = ksp * 8 + q;
            uint32_t af[4][4];
#pragma unroll
            for (int mi = 0; mi < 4; mi++)
                ldsm4(af[mi], stg_u + aoff[mi] + ksp * 32);
            uint32_t bf[NJ][2];
            if (NT) {
#pragma unroll
                for (int njp = 0; njp < 2; njp++) {
                    uint32_t t4[4];
                    ldsm4(t4, stg_u + boff[njp] + ksp * 32);
                    bf[2 * njp][0]     = t4[0];
                    bf[2 * njp][1]     = t4[1];
                    bf[2 * njp + 1][0] = t4[2];
                    bf[2 * njp + 1][1] = t4[3];
                }
            } else {
#pragma unroll
                for (int nj = 0; nj < NJ; nj++) {
                    const float* bp = bs + kq * 136 + wn + nj * 8 + g;
                    bf[nj][0] = __float_as_uint(bp[0]);
                    bf[nj][1] = __float_as_uint(bp[4 * 136]);
                }
            }
#pragma unroll
            for (int mi = 0; mi < 4; mi++)
#pragma unroll
                for (int nj = 0; nj < NJ; nj++)
                    mma_tf32(acc[mi][nj], af[mi], bf[nj]);
        }
    }

    // epilogue
#pragma unroll
    for (int mi = 0; mi < 4; mi++) {
#pragma unroll
        for (int hh = 0; hh < 2; hh++) {
            size_t row = (size_t)(m0 + wm + mi * 16 + g + hh * 8);
#pragma unroll
            for (int nj = 0; nj < NJ; nj++) {
                int col = n0 + wn + nj * 8 + 2 * q;
                float v0 = acc[mi][nj][hh * 2 + 0];
                float v1 = acc[mi][nj][hh * 2 + 1];
                if (EPI == 1) {
                    v0 *= alpha; v1 *= alpha;
                    *(float2*)(C + row * ldc + col) = make_float2(v0, v1);
                } else if (EPI == 2) {
                    *(float2*)(C + row * ldc + col) = make_float2(rnaf(v0), rnaf(v1));
                } else if (EPI == 3) {
                    v0 = xres[row * ldc + col]     + gate[col]     * (v0 + bias[col]);
                    v1 = xres[row * ldc + col + 1] + gate[col + 1] * (v1 + bias[col + 1]);
                    *(float2*)(C + row * ldc + col) = make_float2(v0, v1);
                } else if (EPI == 4) {
                    v0 += bias[col]; v1 += bias[col + 1];
                    if (col < QKV_) {
                        *(float2*)(C + row * QKV_ + col) =
                            make_float2(rnaf(v0), rnaf(v1));
                    } else {
                        *(float2*)(C2 + row * CAT_ + D_ + (col - QKV_)) =
                            make_float2(rnaf(gelu_tanh(v0)), rnaf(gelu_tanh(v1)));
                    }
                }
            }
        }
    }
}

// stage bytes x4 stages
#define SMEM_NN ((128 * 36 + 32 * 136) * 4 * 4)   // 143360
#define SMEM_NT ((128 * 36 + 128 * 36) * 4 * 4)   // 147456

// ---------------------------------------------------------------------------
// launcher
// ---------------------------------------------------------------------------
extern "C" void kernel_launch(void* const* d_in, const int* in_sizes, int n_in,
                              void* d_out, int out_size) {
    const float* x      = (const float*)d_in[0];
    const float* vec    = (const float*)d_in[1];
    const float* pe     = (const float*)d_in[2];
    const float* w_mod  = (const float*)d_in[3];
    const float* b_mod  = (const float*)d_in[4];
    const float* w1     = (const float*)d_in[5];
    const float* b1     = (const float*)d_in[6];
    const float* w2     = (const float*)d_in[7];
    const float* b2     = (const float*)d_in[8];
    const float* qscale = (const float*)d_in[9];
    const float* kscale = (const float*)d_in[10];
    float* out = (float*)d_out;

    float *sv, *m, *xmod, *h, *S, *cat, *w1r, *w2r;
    cudaGetSymbolAddress((void**)&sv,   g_sv);
    cudaGetSymbolAddress((void**)&m,    g_m);
    cudaGetSymbolAddress((void**)&xmod, g_xmod);
    cudaGetSymbolAddress((void**)&h,    g_h);
    cudaGetSymbolAddress((void**)&S,    g_S);
    cudaGetSymbolAddress((void**)&cat,  g_cat);
    cudaGetSymbolAddress((void**)&w1r,  g_w1r);
    cudaGetSymbolAddress((void**)&w2r,  g_w2r);

    cudaFuncSetAttribute(gemm_cp<4, false>,
                         cudaFuncAttributeMaxDynamicSharedMemorySize, SMEM_NN);
    cudaFuncSetAttribute(gemm_cp<1, true>,
                         cudaFuncAttributeMaxDynamicSharedMemorySize, SMEM_NT);
    cudaFuncSetAttribute(gemm_cp<2, false>,
                         cudaFuncAttributeMaxDynamicSharedMemorySize, SMEM_NN);
    cudaFuncSetAttribute(gemm_cp<3, false>,
                         cudaFuncAttributeMaxDynamicSharedMemorySize, SMEM_NN);

    // 0. pre-round weights to tf32
    wround<<<592, 256>>>((const float4*)w1, (float4*)w1r, (int)((size_t)D_ * W1N_ / 4));
    wround<<<592, 256>>>((const float4*)w2, (float4*)w2r, (int)((size_t)CAT_ * D_ / 4));
    // 1. sv = silu(vec); m = b_mod
    silu_init<<<(3 * D_) / 256, 256>>>(vec, b_mod, sv, m);
    // 2. m += sv @ w_mod  (K split 16 ways)
    mod_gemv<<<dim3(72, 16), 128>>>(sv, w_mod, m);
    // 3. layernorm + modulate (rounded)
    ln_mod<<<L_, 256>>>(x, m, xmod);
    // 4. GEMM1: qkv -> h, gelu(mlp) -> cat[:, D:]
    gemm_cp<4, false><<<dim3(L_ / 128, W1N_ / 128), 256, SMEM_NN>>>(
        xmod, w1r, h, cat, D_, D_, W1N_, 0, 0, 0, 0, 1.0f, b1, nullptr, nullptr);
    // 5. q/k rmsnorm + rope (rounded)
    rmsrope<<<dim3(L_, H_), 64>>>(h, pe, qscale, kscale);
    // 6. S = Q @ K^T * Dh^-0.5
    gemm_cp<1, true><<<dim3(L_ / 128, L_ / 128, H_), 256, SMEM_NT>>>(
        h, h + D_, S, nullptr, DH_, QKV_, QKV_, L_,
        (long long)DH_, (long long)DH_, (long long)L_ * L_,
        0.08838834764831845f, nullptr, nullptr, nullptr);
    // 7. softmax (rounded probs)
    softmax2048<<<H_ * L_, 256>>>(S);
    // 8. PV: attn -> cat[:, 0:D]
    gemm_cp<2, false><<<dim3(L_ / 128, 1, H_), 256, SMEM_NN>>>(
        S, h + 2 * D_, cat, nullptr, L_, L_, QKV_, CAT_,
        (long long)L_ * L_, (long long)DH_, (long long)DH_,
        1.0f, nullptr, nullptr, nullptr);
    // 9. out = x + gate * (cat @ w2 + b2)
    gemm_cp<3, false><<<dim3(L_ / 128, D_ / 128), 256, SMEM_NN>>>(
        cat, w2r, out, nullptr, CAT_, CAT_, D_, D_, 0, 0, 0, 1.0f, b2, x, m + 2 * D_);
}

// round 15
// speedup vs baseline: 1.0144x; 1.0144x over previous
#include <cuda_runtime.h>
#include <cuda_bf16.h>
#include <math.h>
#include <stdint.h>

// ---------------------------------------------------------------------------
// SingleStreamBlock — tf32 mma.sync + cp.async (BK=16), per-GEMM tuned:
// GEMM1/QK: BN=256, 1 CTA/SM, ldmatrix A (+B for NT). PV/GEMM2: BN=128,
// 2 CTAs/SM. Weights pre-rounded; activations rounded at source.
// Shapes: B=1, L=2048, D=3072, H=24, Dh=128, QKV=9216, CAT=15360
// ---------------------------------------------------------------------------

#define L_   2048
#define D_   3072
#define H_   24
#define DH_  128
#define QKV_ 9216
#define W1N_ 21504      // QKV + 4*D
#define CAT_ 15360      // D + 4*D
#define EPS_ 1e-6f

// Scratch (device globals: allocation-free)
__device__ float g_sv[D_];
__device__ float g_m[3 * D_];
__device__ float g_xmod[(size_t)L_ * D_];
__device__ float g_h[(size_t)L_ * QKV_];        // compact qkv
__device__ float g_S[(size_t)H_ * L_ * L_];
__device__ float g_cat[(size_t)L_ * CAT_];      // [attn | gelu(mlp)]
__device__ float g_w1r[(size_t)D_ * W1N_];      // tf32-rounded w1
__device__ float g_w2r[(size_t)CAT_ * D_];      // tf32-rounded w2

__device__ __forceinline__ uint32_t f2tf32(float x) {
    uint32_t r;
    asm("cvt.rna.tf32.f32 %0, %1;" : "=r"(r) : "f"(x));
    return r;
}
__device__ __forceinline__ float rnaf(float x) {
    return __uint_as_float(f2tf32(x));
}

// ---------------------------------------------------------------------------
// weight pre-round
// ---------------------------------------------------------------------------
__global__ void wround(const float4* __restrict__ w, float4* __restrict__ o, int n4) {
    int i = blockIdx.x * blockDim.x + threadIdx.x;
    int stride = gridDim.x * blockDim.x;
    for (; i < n4; i += stride) {
        float4 v = w[i];
        o[i] = make_float4(rnaf(v.x), rnaf(v.y), rnaf(v.z), rnaf(v.w));
    }
}

// ---------------------------------------------------------------------------
// small elementwise / reduction kernels
// ---------------------------------------------------------------------------
__global__ void silu_init(const float* __restrict__ v, const float* __restrict__ b,
                          float* __restrict__ sv, float* __restrict__ m) {
    int i = blockIdx.x * blockDim.x + threadIdx.x;
    if (i < D_) {
        float x = v[i];
        sv[i] = x / (1.0f + expf(-x));
    }
    if (i < 3 * D_) m[i] = b[i];
}

// partial dot over i-chunk of 192, atomicAdd into m. grid (72, 16), 128 thr
__global__ void mod_gemv(const float* __restrict__ sv, const float* __restrict__ w,
                         float* __restrict__ m) {
    __shared__ float s[192];
    int i0 = blockIdx.y * 192;
    for (int i = threadIdx.x; i < 192; i += 128) s[i] = sv[i0 + i];
    __syncthreads();
    int j = blockIdx.x * 128 + threadIdx.x;
    float acc = 0.f;
#pragma unroll 8
    for (int i = 0; i < 192; i++) acc += s[i] * w[(size_t)(i0 + i) * (3 * D_) + j];
    atomicAdd(&m[j], acc);
}

__global__ void ln_mod(const float* __restrict__ x, const float* __restrict__ m,
                       float* __restrict__ xmod) {
    __shared__ float r1[8], r2[8], bc[2];
    int row = blockIdx.x, t = threadIdx.x;
    const float* xr = x + (size_t)row * D_;
    float sum = 0.f, ss = 0.f;
    for (int i = t; i < D_; i += 256) {
        float v = xr[i];
        sum += v; ss += v * v;
    }
#pragma unroll
    for (int o = 16; o > 0; o >>= 1) {
        sum += __shfl_xor_sync(0xffffffffu, sum, o);
        ss  += __shfl_xor_sync(0xffffffffu, ss,  o);
    }
    if ((t & 31) == 0) { r1[t >> 5] = sum; r2[t >> 5] = ss; }
    __syncthreads();
    if (t == 0) {
        float a = 0.f, b = 0.f;
        for (int w = 0; w < 8; w++) { a += r1[w]; b += r2[w]; }
        bc[0] = a; bc[1] = b;
    }
    __syncthreads();
    float mu  = bc[0] * (1.0f / D_);
    float var = bc[1] * (1.0f / D_) - mu * mu;
    float inv = rsqrtf(var + EPS_);
    const float* shift = m;
    const float* scale = m + D_;
    float* orow = xmod + (size_t)row * D_;
    for (int i = t; i < D_; i += 256) {
        float v = (xr[i] - mu) * inv;
        orow[i] = rnaf((1.0f + scale[i]) * v + shift[i]);
    }
}

// RMSNorm + RoPE for q,k in compact h [L][QKV_]; tf32-rounded
__global__ void rmsrope(float* __restrict__ h, const float* __restrict__ pe,
                        const float* __restrict__ qs, const float* __restrict__ ks) {
    __shared__ float red[2];
    int l = blockIdx.x, hh = blockIdx.y, t = threadIdx.x;
    float* base = h + (size_t)l * QKV_ + hh * DH_;
    const float* p = pe + (size_t)l * 256 + t * 4;
    for (int s = 0; s < 2; s++) {
        float* ptr = base + s * D_;
        const float* g = s ? ks : qs;
        float a = ptr[2 * t], b = ptr[2 * t + 1];
        float sq = a * a + b * b;
#pragma unroll
        for (int o = 16; o > 0; o >>= 1) sq += __shfl_xor_sync(0xffffffffu, sq, o);
        if ((t & 31) == 0) red[t >> 5] = sq;
        __syncthreads();
        float tot = red[0] + red[1];
        float r = rsqrtf(tot * (1.0f / DH_) + EPS_);
        float na = a * r * g[2 * t];
        float nb = b * r * g[2 * t + 1];
        ptr[2 * t]     = rnaf(p[0] * na + p[1] * nb);
        ptr[2 * t + 1] = rnaf(p[2] * na + p[3] * nb);
        __syncthreads();
    }
}

__global__ void softmax2048(float* __restrict__ S) {
    __shared__ float r[8], bc;
    int t = threadIdx.x;
    float* row = S + (size_t)blockIdx.x * L_;
    float v[8];
    float mx = -1e30f;
#pragma unroll
    for (int i = 0; i < 8; i++) { v[i] = row[t + i * 256]; mx = fmaxf(mx, v[i]); }
#pragma unroll
    for (int o = 16; o > 0; o >>= 1) mx = fmaxf(mx, __shfl_xor_sync(0xffffffffu, mx, o));
    if ((t & 31) == 0) r[t >> 5] = mx;
    __syncthreads();
    if (t == 0) {
        float m2 = r[0];
        for (int w = 1; w < 8; w++) m2 = fmaxf(m2, r[w]);
        bc = m2;
    }
    __syncthreads();
    mx = bc;
    float sum = 0.f;
#pragma unroll
    for (int i = 0; i < 8; i++) { v[i] = expf(v[i] - mx); sum += v[i]; }
#pragma unroll
    for (int o = 16; o > 0; o >>= 1) sum += __shfl_xor_sync(0xffffffffu, sum, o);
    if ((t & 31) == 0) r[t >> 5] = sum;
    __syncthreads();
    if (t == 0) {
        float s2 = 0.f;
        for (int w = 0; w < 8; w++) s2 += r[w];
        bc = s2;
    }
    __syncthreads();
    float inv = 1.0f / bc;
#pragma unroll
    for (int i = 0; i < 8; i++) row[t + i * 256] = rnaf(v[i] * inv);
}

__device__ __forceinline__ float gelu_tanh(float x) {
    float x3 = x * x * x;
    return 0.5f * x * (1.0f + tanhf(0.7978845608028654f * (x + 0.044715f * x3)));
}

// ---------------------------------------------------------------------------
// tf32 mma.sync GEMM: cp.async 4-stage (BK=16) + ldmatrix A (+B for NT).
// 256 thr = 8 warps (2m x 4n), warp tile 64 x (BN/4). MINB = min CTAs/SM.
// A smem [m][k] stride 20 (ldmatrix). B NT [n][k] stride 20 (ldmatrix).
// B NN [k][n] stride BN+8 (scalar LDS, conflict-free), raw tf32 bits.
// EPI 1:*alpha | 2: rna (PV->cat) | 3: xres+gate*(acc+bias) | 4: h|gelu->cat
// ---------------------------------------------------------------------------
#define CPA16(dst, src) \
    asm volatile("cp.async.cg.shared.global [%0], [%1], 16;" :: "r"(dst), "l"(src))
#define CP_COMMIT() asm volatile("cp.async.commit_group;" ::: "memory")
#define CP_WAIT2()  asm volatile("cp.async.wait_group 2;" ::: "memory")

__device__ __forceinline__ void mma_tf32(float c[4], const uint32_t a[4],
                                         const uint32_t b[2]) {
    asm volatile(
        "mma.sync.aligned.m16n8k8.row.col.f32.tf32.tf32.f32 "
        "{%0,%1,%2,%3}, {%4,%5,%6,%7}, {%8,%9}, {%0,%1,%2,%3};"
        : "+f"(c[0]), "+f"(c[1]), "+f"(c[2]), "+f"(c[3])
        : "r"(a[0]), "r"(a[1]), "r"(a[2]), "r"(a[3]), "r"(b[0]), "r"(b[1]));
}
__device__ __forceinline__ void ldsm4(uint32_t* r, uint32_t addr) {
    asm volatile("ldmatrix.sync.aligned.m8n8.x4.shared.b16 {%0,%1,%2,%3}, [%4];"
                 : "=r"(r[0]), "=r"(r[1]), "=r"(r[2]), "=r"(r[3]) : "r"(addr));
}

template <int EPI, bool NT, int BN, int MINB>
__global__ __launch_bounds__(256, MINB) void gemm_cp(
    const float* __restrict__ A, const float* __restrict__ B, float* __restrict__ C,
    float* __restrict__ C2,
    int K, int lda, int ldb, int ldc,
    long long sA, long long sB, long long sC, float alpha,
    const float* __restrict__ bias, const float* __restrict__ xres,
    const float* __restrict__ gate)
{
    constexpr int AW = 128 * 20;                         // A stage words
    constexpr int BW = NT ? BN * 20 : 16 * (BN + 8);     // B stage words
    constexpr int STGW = AW + BW;
    constexpr int NJ = BN / 32;
    extern __shared__ float sm[];

    A += (long long)blockIdx.z * sA;
    B += (long long)blockIdx.z * sB;
    C += (long long)blockIdx.z * sC;
    const int m0 = blockIdx.x * 128, n0 = blockIdx.y * BN;
    const int tid = threadIdx.x;
    const int warp = tid >> 5, lane = tid & 31;
    const int wm = (warp & 1) * 64;
    const int wn = (warp >> 1) * (BN / 4);
    const int g = lane >> 2, q = lane & 3;

    const uint32_t sbase = (uint32_t)__cvta_generic_to_shared(sm);

    // ldmatrix byte offsets (stage-relative)
    int aoff[4][2];
#pragma unroll
    for (int mi = 0; mi < 4; mi++)
#pragma unroll
        for (int ksp = 0; ksp < 2; ksp++)
            aoff[mi][ksp] = ((wm + mi * 16 + ((lane >> 3) & 1) * 8 + (lane & 7)) * 20
                             + ksp * 8 + ((lane >> 4) & 1) * 4) * 4;
    int boff[NJ / 2 > 0 ? NJ / 2 : 1][2];
    if (NT) {
#pragma unroll
        for (int njp = 0; njp < NJ / 2; njp++)
#pragma unroll
            for (int ksp = 0; ksp < 2; ksp++)
                boff[njp][ksp] = AW * 4 +
                    ((wn + njp * 16 + ((lane >> 4) & 1) * 8 + (lane & 7)) * 20
                     + ksp * 8 + ((lane >> 3) & 1) * 4) * 4;
    }

    float acc[4][NJ][4];
#pragma unroll
    for (int mi = 0; mi < 4; mi++)
#pragma unroll
        for (int nj = 0; nj < NJ; nj++)
#pragma unroll
            for (int e = 0; e < 4; e++) acc[mi][nj][e] = 0.f;

    const int nk = K >> 4;

    auto issue = [&](int kt, int s) {
        const uint32_t as = sbase + (uint32_t)(s * STGW * 4);
        const uint32_t bs = as + AW * 4;
        const int k0 = kt << 4;
#pragma unroll
        for (int i = 0; i < 2; i++) {
            int ch = tid + 256 * i;
            int r = ch >> 2, c = ch & 3;
            CPA16(as + (uint32_t)(r * 80 + c * 16),
                  A + (size_t)(m0 + r) * lda + k0 + c * 4);
        }
        if (NT) {
#pragma unroll
            for (int i = 0; i < BN / 64; i++) {
                int ch = tid + 256 * i;
                int r = ch >> 2, c = ch & 3;
                CPA16(bs + (uint32_t)(r * 80 + c * 16),
                      B + (size_t)(n0 + r) * ldb + k0 + c * 4);
            }
        } else {
#pragma unroll
            for (int i = 0; i < BN / 64; i++) {
                int ch = tid + 256 * i;
                int r = ch / (BN / 4), c = ch % (BN / 4);
                CPA16(bs + (uint32_t)(r * (BN + 8) * 4 + c * 16),
                      B + (size_t)(k0 + r) * ldb + n0 + c * 4);
            }
        }
    };

    for (int s = 0; s < 3; s++) {
        if (s < nk) issue(s, s);
        CP_COMMIT();
    }

    for (int it = 0; it < nk; it++) {
        CP_WAIT2();
        __syncthreads();
        if (it + 3 < nk) issue(it + 3, (it + 3) & 3);
        CP_COMMIT();

        const uint32_t stg_u = sbase + (uint32_t)((it & 3) * STGW * 4);
        const float* bs = sm + (size_t)(it & 3) * STGW + AW;
#pragma unroll
        for (int ksp = 0; ksp < 2; ksp++) {
            const int kq = ksp * 8 + q;
            uint32_t af[4][4];
#pragma unroll
            for (int mi = 0; mi < 4; mi++) ldsm4(af[mi], stg_u + aoff[mi][ksp]);
            uint32_t bf[NJ][2];
            if (NT) {
#pragma unroll
                for (int njp = 0; njp < NJ / 2; njp++) {
                    uint32_t t4[4];
                    ldsm4(t4, stg_u + boff[njp][ksp]);
                    bf[2 * njp][0]     = t4[0];
                    bf[2 * njp][1]     = t4[1];
                    bf[2 * njp + 1][0] = t4[2];
                    bf[2 * njp + 1][1] = t4[3];
                }
            } else {
#pragma unroll
                for (int nj = 0; nj < NJ; nj++) {
                    const float* bp = bs + kq * (BN + 8) + wn + nj * 8 + g;
                    bf[nj][0] = __float_as_uint(bp[0]);
                    bf[nj][1] = __float_as_uint(bp[4 * (BN + 8)]);
                }
            }
#pragma unroll
            for (int mi = 0; mi < 4; mi++)
#pragma unroll
                for (int nj = 0; nj < NJ; nj++)
                    mma_tf32(acc[mi][nj], af[mi], bf[nj]);
        }
    }

    // epilogue
#pragma unroll
    for (int mi = 0; mi < 4; mi++) {
#pragma unroll
        for (int hh = 0; hh < 2; hh++) {
            size_t row = (size_t)(m0 + wm + mi * 16 + g + hh * 8);
#pragma unroll
            for (int nj = 0; nj < NJ; nj++) {
                int col = n0 + wn + nj * 8 + 2 * q;
                float v0 = acc[mi][nj][hh * 2 + 0];
                float v1 = acc[mi][nj][hh * 2 + 1];
                if (EPI == 1) {
                    v0 *= alpha; v1 *= alpha;
                    *(float2*)(C + row * ldc + col) = make_float2(v0, v1);
                } else if (EPI == 2) {
                    *(float2*)(C + row * ldc + col) = make_float2(rnaf(v0), rnaf(v1));
                } else if (EPI == 3) {
                    v0 = xres[row * ldc + col]     + gate[col]     * (v0 + bias[col]);
                    v1 = xres[row * ldc + col + 1] + gate[col + 1] * (v1 + bias[col + 1]);
                    *(float2*)(C + row * ldc + col) = make_float2(v0, v1);
                } else if (EPI == 4) {
                    v0 += bias[col]; v1 += bias[col + 1];
                    if (col < QKV_) {
                        *(float2*)(C + row * QKV_ + col) =
                            make_float2(rnaf(v0), rnaf(v1));
                    } else {
                        *(float2*)(C2 + row * CAT_ + D_ + (col - QKV_)) =
                            make_float2(rnaf(gelu_tanh(v0)), rnaf(gelu_tanh(v1)));
                    }
                }
            }
        }
    }
}

// stage bytes x4 stages
#define SMEM_NN256 ((128 * 20 + 16 * 264) * 4 * 4)   // 108544
#define SMEM_NT256 ((128 * 20 + 256 * 20) * 4 * 4)   // 122880
#define SMEM_NN128 ((128 * 20 + 16 * 136) * 4 * 4)   // 75776

// ---------------------------------------------------------------------------
// launcher
// ---------------------------------------------------------------------------
extern "C" void kernel_launch(void* const* d_in, const int* in_sizes, int n_in,
                              void* d_out, int out_size) {
    const float* x      = (const float*)d_in[0];
    const float* vec    = (const float*)d_in[1];
    const float* pe     = (const float*)d_in[2];
    const float* w_mod  = (const float*)d_in[3];
    const float* b_mod  = (const float*)d_in[4];
    const float* w1     = (const float*)d_in[5];
    const float* b1     = (const float*)d_in[6];
    const float* w2     = (const float*)d_in[7];
    const float* b2     = (const float*)d_in[8];
    const float* qscale = (const float*)d_in[9];
    const float* kscale = (const float*)d_in[10];
    float* out = (float*)d_out;

    float *sv, *m, *xmod, *h, *S, *cat, *w1r, *w2r;
    cudaGetSymbolAddress((void**)&sv,   g_sv);
    cudaGetSymbolAddress((void**)&m,    g_m);
    cudaGetSymbolAddress((void**)&xmod, g_xmod);
    cudaGetSymbolAddress((void**)&h,    g_h);
    cudaGetSymbolAddress((void**)&S,    g_S);
    cudaGetSymbolAddress((void**)&cat,  g_cat);
    cudaGetSymbolAddress((void**)&w1r,  g_w1r);
    cudaGetSymbolAddress((void**)&w2r,  g_w2r);

    cudaFuncSetAttribute(gemm_cp<4, false, 256, 1>,
                         cudaFuncAttributeMaxDynamicSharedMemorySize, SMEM_NN256);
    cudaFuncSetAttribute(gemm_cp<1, true, 256, 1>,
                         cudaFuncAttributeMaxDynamicSharedMemorySize, SMEM_NT256);
    cudaFuncSetAttribute(gemm_cp<2, false, 128, 2>,
                         cudaFuncAttributeMaxDynamicSharedMemorySize, SMEM_NN128);
    cudaFuncSetAttribute(gemm_cp<3, false, 128, 2>,
                         cudaFuncAttributeMaxDynamicSharedMemorySize, SMEM_NN128);

    // 0. pre-round weights to tf32
    wround<<<592, 256>>>((const float4*)w1, (float4*)w1r, (int)((size_t)D_ * W1N_ / 4));
    wround<<<592, 256>>>((const float4*)w2, (float4*)w2r, (int)((size_t)CAT_ * D_ / 4));
    // 1. sv = silu(vec); m = b_mod
    silu_init<<<(3 * D_) / 256, 256>>>(vec, b_mod, sv, m);
    // 2. m += sv @ w_mod  (K split 16 ways)
    mod_gemv<<<dim3(72, 16), 128>>>(sv, w_mod, m);
    // 3. layernorm + modulate (rounded)
    ln_mod<<<L_, 256>>>(x, m, xmod);
    // 4. GEMM1: qkv -> h, gelu(mlp) -> cat[:, D:]   (BN=256, ldmatrix A)
    gemm_cp<4, false, 256, 1><<<dim3(L_ / 128, W1N_ / 256), 256, SMEM_NN256>>>(
        xmod, w1r, h, cat, D_, D_, W1N_, 0, 0, 0, 0, 1.0f, b1, nullptr, nullptr);
    // 5. q/k rmsnorm + rope (rounded)
    rmsrope<<<dim3(L_, H_), 64>>>(h, pe, qscale, kscale);
    // 6. S = Q @ K^T * Dh^-0.5   (BN=256 NT, ldmatrix A+B)
    gemm_cp<1, true, 256, 1><<<dim3(L_ / 128, L_ / 256, H_), 256, SMEM_NT256>>>(
        h, h + D_, S, nullptr, DH_, QKV_, QKV_, L_,
        (long long)DH_, (long long)DH_, (long long)L_ * L_,
        0.08838834764831845f, nullptr, nullptr, nullptr);
    // 7. softmax (rounded probs)
    softmax2048<<<H_ * L_, 256>>>(S);
    // 8. PV: attn -> cat[:, 0:D]   (BN=128, 2 CTAs/SM)
    gemm_cp<2, false, 128, 2><<<dim3(L_ / 128, 1, H_), 256, SMEM_NN128>>>(
        S, h + 2 * D_, cat, nullptr, L_, L_, QKV_, CAT_,
        (long long)L_ * L_, (long long)DH_, (long long)DH_,
        1.0f, nullptr, nullptr, nullptr);
    // 9. out = x + gate * (cat @ w2 + b2)   (BN=128, 2 CTAs/SM)
    gemm_cp<3, false, 128, 2><<<dim3(L_ / 128, D_ / 128), 256, SMEM_NN128>>>(
        cat, w2r, out, nullptr, CAT_, CAT_, D_, D_, 0, 0, 0, 1.0f, b2, x, m + 2 * D_);
}

// round 16
// speedup vs baseline: 1.0680x; 1.0528x over previous
#include <cuda_runtime.h>
#include <cuda_bf16.h>
#include <math.h>
#include <stdint.h>

// ---------------------------------------------------------------------------
// SingleStreamBlock — tf32 mma.sync GEMMs + FUSED flash attention (no S
// buffer, no softmax kernel). Weights pre-rounded; activations rounded at
// source. Shapes: B=1, L=2048, D=3072, H=24, Dh=128, QKV=9216, CAT=15360
// ---------------------------------------------------------------------------

#define L_   2048
#define D_   3072
#define H_   24
#define DH_  128
#define QKV_ 9216
#define W1N_ 21504      // QKV + 4*D
#define CAT_ 15360      // D + 4*D
#define EPS_ 1e-6f

// Scratch (device globals: allocation-free)
__device__ float g_sv[D_];
__device__ float g_m[3 * D_];
__device__ float g_xmod[(size_t)L_ * D_];
__device__ float g_h[(size_t)L_ * QKV_];        // compact qkv
__device__ float g_cat[(size_t)L_ * CAT_];      // [attn | gelu(mlp)]
__device__ float g_w1r[(size_t)D_ * W1N_];      // tf32-rounded w1
__device__ float g_w2r[(size_t)CAT_ * D_];      // tf32-rounded w2

__device__ __forceinline__ uint32_t f2tf32(float x) {
    uint32_t r;
    asm("cvt.rna.tf32.f32 %0, %1;" : "=r"(r) : "f"(x));
    return r;
}
__device__ __forceinline__ float rnaf(float x) {
    return __uint_as_float(f2tf32(x));
}

// ---------------------------------------------------------------------------
// weight pre-round
// ---------------------------------------------------------------------------
__global__ void wround(const float4* __restrict__ w, float4* __restrict__ o, int n4) {
    int i = blockIdx.x * blockDim.x + threadIdx.x;
    int stride = gridDim.x * blockDim.x;
    for (; i < n4; i += stride) {
        float4 v = w[i];
        o[i] = make_float4(rnaf(v.x), rnaf(v.y), rnaf(v.z), rnaf(v.w));
    }
}

// ---------------------------------------------------------------------------
// small elementwise / reduction kernels
// ---------------------------------------------------------------------------
__global__ void silu_init(const float* __restrict__ v, const float* __restrict__ b,
                          float* __restrict__ sv, float* __restrict__ m) {
    int i = blockIdx.x * blockDim.x + threadIdx.x;
    if (i < D_) {
        float x = v[i];
        sv[i] = x / (1.0f + expf(-x));
    }
    if (i < 3 * D_) m[i] = b[i];
}

__global__ void mod_gemv(const float* __restrict__ sv, const float* __restrict__ w,
                         float* __restrict__ m) {
    __shared__ float s[192];
    int i0 = blockIdx.y * 192;
    for (int i = threadIdx.x; i < 192; i += 128) s[i] = sv[i0 + i];
    __syncthreads();
    int j = blockIdx.x * 128 + threadIdx.x;
    float acc = 0.f;
#pragma unroll 8
    for (int i = 0; i < 192; i++) acc += s[i] * w[(size_t)(i0 + i) * (3 * D_) + j];
    atomicAdd(&m[j], acc);
}

__global__ void ln_mod(const float* __restrict__ x, const float* __restrict__ m,
                       float* __restrict__ xmod) {
    __shared__ float r1[8], r2[8], bc[2];
    int row = blockIdx.x, t = threadIdx.x;
    const float* xr = x + (size_t)row * D_;
    float sum = 0.f, ss = 0.f;
    for (int i = t; i < D_; i += 256) {
        float v = xr[i];
        sum += v; ss += v * v;
    }
#pragma unroll
    for (int o = 16; o > 0; o >>= 1) {
        sum += __shfl_xor_sync(0xffffffffu, sum, o);
        ss  += __shfl_xor_sync(0xffffffffu, ss,  o);
    }
    if ((t & 31) == 0) { r1[t >> 5] = sum; r2[t >> 5] = ss; }
    __syncthreads();
    if (t == 0) {
        float a = 0.f, b = 0.f;
        for (int w = 0; w < 8; w++) { a += r1[w]; b += r2[w]; }
        bc[0] = a; bc[1] = b;
    }
    __syncthreads();
    float mu  = bc[0] * (1.0f / D_);
    float var = bc[1] * (1.0f / D_) - mu * mu;
    float inv = rsqrtf(var + EPS_);
    const float* shift = m;
    const float* scale = m + D_;
    float* orow = xmod + (size_t)row * D_;
    for (int i = t; i < D_; i += 256) {
        float v = (xr[i] - mu) * inv;
        orow[i] = rnaf((1.0f + scale[i]) * v + shift[i]);
    }
}

// RMSNorm + RoPE for q,k in compact h [L][QKV_]; tf32-rounded
__global__ void rmsrope(float* __restrict__ h, const float* __restrict__ pe,
                        const float* __restrict__ qs, const float* __restrict__ ks) {
    __shared__ float red[2];
    int l = blockIdx.x, hh = blockIdx.y, t = threadIdx.x;
    float* base = h + (size_t)l * QKV_ + hh * DH_;
    const float* p = pe + (size_t)l * 256 + t * 4;
    for (int s = 0; s < 2; s++) {
        float* ptr = base + s * D_;
        const float* g = s ? ks : qs;
        float a = ptr[2 * t], b = ptr[2 * t + 1];
        float sq = a * a + b * b;
#pragma unroll
        for (int o = 16; o > 0; o >>= 1) sq += __shfl_xor_sync(0xffffffffu, sq, o);
        if ((t & 31) == 0) red[t >> 5] = sq;
        __syncthreads();
        float tot = red[0] + red[1];
        float r = rsqrtf(tot * (1.0f / DH_) + EPS_);
        float na = a * r * g[2 * t];
        float nb = b * r * g[2 * t + 1];
        ptr[2 * t]     = rnaf(p[0] * na + p[1] * nb);
        ptr[2 * t + 1] = rnaf(p[2] * na + p[3] * nb);
        __syncthreads();
    }
}

__device__ __forceinline__ float gelu_tanh(float x) {
    float x3 = x * x * x;
    return 0.5f * x * (1.0f + tanhf(0.7978845608028654f * (x + 0.044715f * x3)));
}

// ---------------------------------------------------------------------------
// mma / ldmatrix / cp.async primitives
// ---------------------------------------------------------------------------
#define CPA16(dst, src) \
    asm volatile("cp.async.cg.shared.global [%0], [%1], 16;" :: "r"(dst), "l"(src))
#define CP_COMMIT() asm volatile("cp.async.commit_group;" ::: "memory")
#define CP_WAIT2()  asm volatile("cp.async.wait_group 2;" ::: "memory")
#define CP_WAIT1()  asm volatile("cp.async.wait_group 1;" ::: "memory")
#define CP_WAIT0()  asm volatile("cp.async.wait_group 0;" ::: "memory")

__device__ __forceinline__ void mma_tf32(float c[4], const uint32_t a[4],
                                         const uint32_t b[2]) {
    asm volatile(
        "mma.sync.aligned.m16n8k8.row.col.f32.tf32.tf32.f32 "
        "{%0,%1,%2,%3}, {%4,%5,%6,%7}, {%8,%9}, {%0,%1,%2,%3};"
        : "+f"(c[0]), "+f"(c[1]), "+f"(c[2]), "+f"(c[3])
        : "r"(a[0]), "r"(a[1]), "r"(a[2]), "r"(a[3]), "r"(b[0]), "r"(b[1]));
}
__device__ __forceinline__ void ldsm4(uint32_t* r, uint32_t addr) {
    asm volatile("ldmatrix.sync.aligned.m8n8.x4.shared.b16 {%0,%1,%2,%3}, [%4];"
                 : "=r"(r[0]), "=r"(r[1]), "=r"(r[2]), "=r"(r[3]) : "r"(addr));
}

// ---------------------------------------------------------------------------
// Fused flash attention. CTA = 128 q-rows x 1 head; grid (16, 24); 256 thr.
// Warp w owns q-rows [16w, 16w+16). Q fragments in registers (loaded once).
// Loop over 32 K/V tiles of 64 rows, cp.async double-buffered.
// Smem words: K0=0 K1=8448 V0=16896 V1=25600 P=34304, total 43008 (172 KB).
// K stride 132 (ldmatrix NT), V stride 136 (scalar NN), P stride 68 (ldmatrix).
// Output written to cat[:, head*128 ...], tf32-rounded.
// ---------------------------------------------------------------------------
#define FA_SMEM (43008 * 4)

__global__ __launch_bounds__(256) void flash_attn(
    const float* __restrict__ h, float* __restrict__ cat)
{
    extern __shared__ float sm[];
    const uint32_t sb = (uint32_t)__cvta_generic_to_shared(sm);
    const int tid = threadIdx.x, warp = tid >> 5, lane = tid & 31;
    const int g = lane >> 2, q = lane & 3;
    const int m0 = blockIdx.x * 128, hd = blockIdx.y;
    const float c2 = 0.08838834764831845f * 1.4426950408889634f;  // scale*log2e

    const float* qg = h + hd * DH_;
    const float* kg = h + D_ + hd * DH_;
    const float* vg = h + 2 * D_ + hd * DH_;

    const uint32_t K0 = sb, K1 = sb + 8448 * 4, V0 = sb + 16896 * 4,
                   V1 = sb + 25600 * 4, PB = sb + 34304 * 4;

    // ---- stage Q (128x128) into smem (K0 region, stride 132), ldmatrix to regs
#pragma unroll
    for (int i = 0; i < 16; i++) {
        int ch = tid + 256 * i;
        int r = ch >> 5, c = ch & 31;
        CPA16(K0 + (uint32_t)(r * 528 + c * 16),
              qg + (size_t)(m0 + r) * QKV_ + c * 4);
    }
    CP_COMMIT();
    CP_WAIT0();
    __syncthreads();

    uint32_t qf[16][4];
    {
        const int qrow = warp * 16 + ((lane >> 3) & 1) * 8 + (lane & 7);
        const uint32_t qb = K0 + (uint32_t)(qrow * 528 + ((lane >> 4) & 1) * 16);
#pragma unroll
        for (int kt = 0; kt < 16; kt++) ldsm4(qf[kt], qb + kt * 32);
    }
    __syncthreads();   // Q region reused for K below

    // ---- state
    float oacc[16][4];
#pragma unroll
    for (int nt = 0; nt < 16; nt++)
#pragma unroll
        for (int e = 0; e < 4; e++) oacc[nt][e] = 0.f;
    float mrow0 = -1e30f, mrow1 = -1e30f, lrow0 = 0.f, lrow1 = 0.f;

    // ldmatrix offsets
    const int krow_off = ((lane >> 4) & 1) * 8 + (lane & 7);    // B NT pattern
    const int kk_off   = ((lane >> 3) & 1) * 4;
    const int prow     = warp * 16 + ((lane >> 3) & 1) * 8 + (lane & 7);  // A pattern
    const uint32_t pbase = PB + (uint32_t)(prow * 272 + ((lane >> 4) & 1) * 16);

    auto kvissue = [&](int j, int b) {
        const float* kp = kg + (size_t)(j * 64) * QKV_;
        const float* vp = vg + (size_t)(j * 64) * QKV_;
        const uint32_t kd = b ? K1 : K0;
        const uint32_t vd = b ? V1 : V0;
#pragma unroll
        for (int i = 0; i < 8; i++) {
            int ch = tid + 256 * i;
            int r = ch >> 5, c = ch & 31;
            CPA16(kd + (uint32_t)(r * 528 + c * 16), kp + (size_t)r * QKV_ + c * 4);
        }
#pragma unroll
        for (int i = 0; i < 8; i++) {
            int ch = tid + 256 * i;
            int r = ch >> 5, c = ch & 31;
            CPA16(vd + (uint32_t)(r * 544 + c * 16), vp + (size_t)r * QKV_ + c * 4);
        }
    };

    kvissue(0, 0);
    CP_COMMIT();

    for (int j = 0; j < 32; j++) {
        const int b = j & 1;
        if (j + 1 < 32) kvissue(j + 1, b ^ 1);
        CP_COMMIT();
        CP_WAIT1();          // group j complete (thread-local)
        __syncthreads();     // all threads' group-j data visible

        const uint32_t kbuf = b ? K1 : K0;
        const uint32_t vbuf_w = b ? 25600u : 16896u;   // word offset of V buf

        // ---- S = Q @ K_j^T  (16 rows x 64 cols per warp)
        float sf[8][4];
#pragma unroll
        for (int nt = 0; nt < 8; nt++)
#pragma unroll
            for (int e = 0; e < 4; e++) sf[nt][e] = 0.f;
#pragma unroll
        for (int ks = 0; ks < 16; ks++) {
            uint32_t kf[8][2];
#pragma unroll
            for (int njp = 0; njp < 4; njp++) {
                uint32_t t4[4];
                ldsm4(t4, kbuf + (uint32_t)((njp * 16 + krow_off) * 528
                                            + ks * 32 + kk_off * 4));
                kf[2 * njp][0]     = t4[0];
                kf[2 * njp][1]     = t4[1];
                kf[2 * njp + 1][0] = t4[2];
                kf[2 * njp + 1][1] = t4[3];
            }
#pragma unroll
            for (int nt = 0; nt < 8; nt++) mma_tf32(sf[nt], qf[ks], kf[nt]);
        }

        // ---- online softmax (rows g and g+8), base-2 domain
        float mx0 = -1e30f, mx1 = -1e30f;
#pragma unroll
        for (int nt = 0; nt < 8; nt++) {
            mx0 = fmaxf(mx0, fmaxf(sf[nt][0], sf[nt][1]));
            mx1 = fmaxf(mx1, fmaxf(sf[nt][2], sf[nt][3]));
        }
#pragma unroll
        for (int o = 1; o <= 2; o <<= 1) {
            mx0 = fmaxf(mx0, __shfl_xor_sync(0xffffffffu, mx0, o));
            mx1 = fmaxf(mx1, __shfl_xor_sync(0xffffffffu, mx1, o));
        }
        float mn0 = fmaxf(mrow0, mx0 * c2);
        float mn1 = fmaxf(mrow1, mx1 * c2);
        float al0 = exp2f(mrow0 - mn0);
        float al1 = exp2f(mrow1 - mn1);
        mrow0 = mn0; mrow1 = mn1;

        float sum0 = 0.f, sum1 = 0.f;
#pragma unroll
        for (int nt = 0; nt < 8; nt++) {
            float p0 = rnaf(exp2f(sf[nt][0] * c2 - mn0));
            float p1 = rnaf(exp2f(sf[nt][1] * c2 - mn0));
            float p2 = rnaf(exp2f(sf[nt][2] * c2 - mn1));
            float p3 = rnaf(exp2f(sf[nt][3] * c2 - mn1));
            sum0 += p0 + p1; sum1 += p2 + p3;
            // store P to per-warp smem strip [row][kv] stride 68 words
            uint32_t a0 = PB + (uint32_t)(((warp * 16 + g) * 68 + nt * 8 + 2 * q) * 4);
            uint32_t a1 = a0 + 8 * 68 * 4;
            asm volatile("st.shared.v2.f32 [%0], {%1,%2};" :: "r"(a0), "f"(p0), "f"(p1));
            asm volatile("st.shared.v2.f32 [%0], {%1,%2};" :: "r"(a1), "f"(p2), "f"(p3));
        }
#pragma unroll
        for (int o = 1; o <= 2; o <<= 1) {
            sum0 += __shfl_xor_sync(0xffffffffu, sum0, o);
            sum1 += __shfl_xor_sync(0xffffffffu, sum1, o);
        }
        lrow0 = lrow0 * al0 + sum0;
        lrow1 = lrow1 * al1 + sum1;
#pragma unroll
        for (int nt = 0; nt < 16; nt++) {
            oacc[nt][0] *= al0; oacc[nt][1] *= al0;
            oacc[nt][2] *= al1; oacc[nt][3] *= al1;
        }
        __syncwarp();

        // ---- O += P @ V_j   (16 rows x 128 cols per warp, k=64)
#pragma unroll
        for (int ks2 = 0; ks2 < 8; ks2++) {
            uint32_t pf[4];
            ldsm4(pf, pbase + ks2 * 32);
            const int kq = ks2 * 8 + q;
            const float* vrow = sm + vbuf_w + kq * 136;
#pragma unroll
            for (int nt = 0; nt < 16; nt++) {
                uint32_t bf[2];
                bf[0] = __float_as_uint(vrow[nt * 8 + g]);
                bf[1] = __float_as_uint(vrow[4 * 136 + nt * 8 + g]);
                mma_tf32(oacc[nt], pf, bf);
            }
        }
        __syncthreads();   // all warps done reading K/V bufs for this iter
    }

    // ---- epilogue: O / l -> cat[:, hd*128 ...]
    float inv0 = 1.0f / lrow0, inv1 = 1.0f / lrow1;
    size_t row0 = (size_t)(m0 + warp * 16 + g);
#pragma unroll
    for (int nt = 0; nt < 16; nt++) {
        int col = hd * DH_ + nt * 8 + 2 * q;
        *(float2*)(cat + row0 * CAT_ + col) =
            make_float2(rnaf(oacc[nt][0] * inv0), rnaf(oacc[nt][1] * inv0));
        *(float2*)(cat + (row0 + 8) * CAT_ + col) =
            make_float2(rnaf(oacc[nt][2] * inv1), rnaf(oacc[nt][3] * inv1));
    }
}

// ---------------------------------------------------------------------------
// tf32 mma.sync GEMM: cp.async 4-stage (BK=16) + ldmatrix A.
// EPI 3: xres+gate*(acc+bias) | 4: qkv->h, gelu(mlp)->cat
// ---------------------------------------------------------------------------
template <int EPI, int BN, int MINB>
__global__ __launch_bounds__(256, MINB) void gemm_cp(
    const float* __restrict__ A, const float* __restrict__ B, float* __restrict__ C,
    float* __restrict__ C2,
    int K, int lda, int ldb, int ldc,
    const float* __restrict__ bias, const float* __restrict__ xres,
    const float* __restrict__ gate)
{
    constexpr int AW = 128 * 20;
    constexpr int BW = 16 * (BN + 8);
    constexpr int STGW = AW + BW;
    constexpr int NJ = BN / 32;
    extern __shared__ float sm[];

    const int m0 = blockIdx.x * 128, n0 = blockIdx.y * BN;
    const int tid = threadIdx.x;
    const int warp = tid >> 5, lane = tid & 31;
    const int wm = (warp & 1) * 64;
    const int wn = (warp >> 1) * (BN / 4);
    const int g = lane >> 2, q = lane & 3;

    const uint32_t sbase = (uint32_t)__cvta_generic_to_shared(sm);

    int aoff[4][2];
#pragma unroll
    for (int mi = 0; mi < 4; mi++)
#pragma unroll
        for (int ksp = 0; ksp < 2; ksp++)
            aoff[mi][ksp] = ((wm + mi * 16 + ((lane >> 3) & 1) * 8 + (lane & 7)) * 20
                             + ksp * 8 + ((lane >> 4) & 1) * 4) * 4;

    float acc[4][NJ][4];
#pragma unroll
    for (int mi = 0; mi < 4; mi++)
#pragma unroll
        for (int nj = 0; nj < NJ; nj++)
#pragma unroll
            for (int e = 0; e < 4; e++) acc[mi][nj][e] = 0.f;

    const int nk = K >> 4;

    auto issue = [&](int kt, int s) {
        const uint32_t as = sbase + (uint32_t)(s * STGW * 4);
        const uint32_t bs = as + AW * 4;
        const int k0 = kt << 4;
#pragma unroll
        for (int i = 0; i < 2; i++) {
            int ch = tid + 256 * i;
            int r = ch >> 2, c = ch & 3;
            CPA16(as + (uint32_t)(r * 80 + c * 16),
                  A + (size_t)(m0 + r) * lda + k0 + c * 4);
        }
#pragma unroll
        for (int i = 0; i < BN / 64; i++) {
            int ch = tid + 256 * i;
            int r = ch / (BN / 4), c = ch % (BN / 4);
            CPA16(bs + (uint32_t)(r * (BN + 8) * 4 + c * 16),
                  B + (size_t)(k0 + r) * ldb + n0 + c * 4);
        }
    };

    for (int s = 0; s < 3; s++) {
        if (s < nk) issue(s, s);
        CP_COMMIT();
    }

    for (int it = 0; it < nk; it++) {
        CP_WAIT2();
        __syncthreads();
        if (it + 3 < nk) issue(it + 3, (it + 3) & 3);
        CP_COMMIT();

        const uint32_t stg_u = sbase + (uint32_t)((it & 3) * STGW * 4);
        const float* bs = sm + (size_t)(it & 3) * STGW + AW;
#pragma unroll
        for (int ksp = 0; ksp < 2; ksp++) {
            const int kq = ksp * 8 + q;
            uint32_t af[4][4];
#pragma unroll
            for (int mi = 0; mi < 4; mi++) ldsm4(af[mi], stg_u + aoff[mi][ksp]);
            uint32_t bf[NJ][2];
#pragma unroll
            for (int nj = 0; nj < NJ; nj++) {
                const float* bp = bs + kq * (BN + 8) + wn + nj * 8 + g;
                bf[nj][0] = __float_as_uint(bp[0]);
                bf[nj][1] = __float_as_uint(bp[4 * (BN + 8)]);
            }
#pragma unroll
            for (int mi = 0; mi < 4; mi++)
#pragma unroll
                for (int nj = 0; nj < NJ; nj++)
                    mma_tf32(acc[mi][nj], af[mi], bf[nj]);
        }
    }

#pragma unroll
    for (int mi = 0; mi < 4; mi++) {
#pragma unroll
        for (int hh = 0; hh < 2; hh++) {
            size_t row = (size_t)(m0 + wm + mi * 16 + g + hh * 8);
#pragma unroll
            for (int nj = 0; nj < NJ; nj++) {
                int col = n0 + wn + nj * 8 + 2 * q;
                float v0 = acc[mi][nj][hh * 2 + 0];
                float v1 = acc[mi][nj][hh * 2 + 1];
                if (EPI == 3) {
                    v0 = xres[row * ldc + col]     + gate[col]     * (v0 + bias[col]);
                    v1 = xres[row * ldc + col + 1] + gate[col + 1] * (v1 + bias[col + 1]);
                    *(float2*)(C + row * ldc + col) = make_float2(v0, v1);
                } else {  // EPI 4
                    v0 += bias[col]; v1 += bias[col + 1];
                    if (col < QKV_) {
                        *(float2*)(C + row * QKV_ + col) =
                            make_float2(rnaf(v0), rnaf(v1));
                    } else {
                        *(float2*)(C2 + row * CAT_ + D_ + (col - QKV_)) =
                            make_float2(rnaf(gelu_tanh(v0)), rnaf(gelu_tanh(v1)));
                    }
                }
            }
        }
    }
}

#define SMEM_NN256 ((128 * 20 + 16 * 264) * 4 * 4)   // 108544
#define SMEM_NN128 ((128 * 20 + 16 * 136) * 4 * 4)   // 75776

// ---------------------------------------------------------------------------
// launcher
// ---------------------------------------------------------------------------
extern "C" void kernel_launch(void* const* d_in, const int* in_sizes, int n_in,
                              void* d_out, int out_size) {
    const float* x      = (const float*)d_in[0];
    const float* vec    = (const float*)d_in[1];
    const float* pe     = (const float*)d_in[2];
    const float* w_mod  = (const float*)d_in[3];
    const float* b_mod  = (const float*)d_in[4];
    const float* w1     = (const float*)d_in[5];
    const float* b1     = (const float*)d_in[6];
    const float* w2     = (const float*)d_in[7];
    const float* b2     = (const float*)d_in[8];
    const float* qscale = (const float*)d_in[9];
    const float* kscale = (const float*)d_in[10];
    float* out = (float*)d_out;

    float *sv, *m, *xmod, *h, *cat, *w1r, *w2r;
    cudaGetSymbolAddress((void**)&sv,   g_sv);
    cudaGetSymbolAddress((void**)&m,    g_m);
    cudaGetSymbolAddress((void**)&xmod, g_xmod);
    cudaGetSymbolAddress((void**)&h,    g_h);
    cudaGetSymbolAddress((void**)&cat,  g_cat);
    cudaGetSymbolAddress((void**)&w1r,  g_w1r);
    cudaGetSymbolAddress((void**)&w2r,  g_w2r);

    cudaFuncSetAttribute(gemm_cp<4, 256, 1>,
                         cudaFuncAttributeMaxDynamicSharedMemorySize, SMEM_NN256);
    cudaFuncSetAttribute(gemm_cp<3, 128, 2>,
                         cudaFuncAttributeMaxDynamicSharedMemorySize, SMEM_NN128);
    cudaFuncSetAttribute(flash_attn,
                         cudaFuncAttributeMaxDynamicSharedMemorySize, FA_SMEM);

    // 0. pre-round weights to tf32
    wround<<<592, 256>>>((const float4*)w1, (float4*)w1r, (int)((size_t)D_ * W1N_ / 4));
    wround<<<592, 256>>>((const float4*)w2, (float4*)w2r, (int)((size_t)CAT_ * D_ / 4));
    // 1. sv = silu(vec); m = b_mod
    silu_init<<<(3 * D_) / 256, 256>>>(vec, b_mod, sv, m);
    // 2. m += sv @ w_mod
    mod_gemv<<<dim3(72, 16), 128>>>(sv, w_mod, m);
    // 3. layernorm + modulate (rounded)
    ln_mod<<<L_, 256>>>(x, m, xmod);
    // 4. GEMM1: qkv -> h (compact), gelu(mlp) -> cat[:, D:]
    gemm_cp<4, 256, 1><<<dim3(L_ / 128, W1N_ / 256), 256, SMEM_NN256>>>(
        xmod, w1r, h, cat, D_, D_, W1N_, 0, b1, nullptr, nullptr);
    // 5. q/k rmsnorm + rope (rounded)
    rmsrope<<<dim3(L_, H_), 64>>>(h, pe, qscale, kscale);
    // 6. fused attention -> cat[:, 0:D]
    flash_attn<<<dim3(L_ / 128, H_), 256, FA_SMEM>>>(h, cat);
    // 7. out = x + gate * (cat @ w2 + b2)
    gemm_cp<3, 128, 2><<<dim3(L_ / 128, D_ / 128), 256, SMEM_NN128>>>(
        cat, w2r, out, nullptr, CAT_, CAT_, D_, D_, b2, x, m + 2 * D_);
}